// round 9
// baseline (speedup 1.0000x reference)
#include <cuda_runtime.h>
#include <cstdint>

#define NB 64
#define NS 512
#define NH 768
#define NL 9
#define NCH 8
#define CHS 64
#define GT 128           // tokens per gemm block (= threads)

typedef unsigned long long ull;

// scratch (static device globals — no allocation)
__device__ float g_feats[NB * NS * NL];
__device__ float g_M[NB * NCH * 81];     // per-(batch,chunk) 9x9 log transfer matrices
__device__ float g_nll[NB];

__device__ __forceinline__ ull ffma2(ull a, ull b, ull c) {
    ull d;
    asm("fma.rn.f32x2 %0, %1, %2, %3;" : "=l"(d) : "l"(a), "l"(b), "l"(c));
    return d;
}

// ---------------------------------------------------------------------------
// Phase 1: feats[tok][l] = hidden[tok] . W[l] + b[l]
// Thread-per-token, hidden double-buffered through smem tiles (coalesced LDG,
// conflict-free STS/LDS via pitch 36), W read as warp-broadcast LDS.128
// (1 wavefront instead of 4) -> crossbar traffic drops below the DRAM floor.
// f32x2 packed FMA over adjacent h-pairs halves FFMA issue.
// ---------------------------------------------------------------------------
__global__ __launch_bounds__(GT, 3) void gemm_kernel(
    const float* __restrict__ hidden, const float* __restrict__ W,
    const float* __restrict__ bias)
{
    __shared__ float s_w[NL * NH];           // 27648 B
    __shared__ float s_h[2][GT][36];         // 36864 B (pitch 36 floats = 144B)

    int tid   = threadIdx.x;
    int tok0  = blockIdx.x * GT;
    int rbase = tid >> 3;                    // 0..15
    int c4    = tid & 7;                     // 0..7

    // stage W into smem (one-time)
    for (int i = tid; i < NL * NH / 4; i += GT)
        ((float4*)s_w)[i] = __ldg((const float4*)W + i);

    // stage chunk 0 of hidden (128 tok x 32 h), coalesced
#pragma unroll
    for (int k = 0; k < 8; k++) {
        int r = k * 16 + rbase;
        float4 v = __ldg((const float4*)(hidden + (size_t)(tok0 + r) * NH + c4 * 4));
        *(float4*)&s_h[0][r][c4 * 4] = v;
    }
    __syncthreads();

    ull acc[NL];
#pragma unroll
    for (int l = 0; l < NL; l++) acc[l] = 0ull;

#pragma unroll 1
    for (int ch = 0; ch < 24; ch++) {
        int cur = ch & 1;

        float4 pf[8];
        if (ch < 23) {                       // prefetch next chunk into regs
#pragma unroll
            for (int k = 0; k < 8; k++) {
                int r = k * 16 + rbase;
                pf[k] = __ldg((const float4*)(hidden + (size_t)(tok0 + r) * NH
                                              + (ch + 1) * 32 + c4 * 4));
            }
        }

        const float* hrow  = s_h[cur][tid];
        const float* wbase = s_w + ch * 32;
#pragma unroll
        for (int s = 0; s < 8; s++) {
            ulonglong2 h2 = *(const ulonglong2*)(hrow + s * 4);
#pragma unroll
            for (int l = 0; l < NL; l++) {
                ulonglong2 w2 = *(const ulonglong2*)(wbase + l * NH + s * 4);
                acc[l] = ffma2(h2.x, w2.x, acc[l]);
                acc[l] = ffma2(h2.y, w2.y, acc[l]);
            }
        }

        if (ch < 23) {                       // store prefetched chunk to other buffer
#pragma unroll
            for (int k = 0; k < 8; k++)
                *(float4*)&s_h[cur ^ 1][k * 16 + rbase][c4 * 4] = pf[k];
        }
        __syncthreads();
    }

    // epilogue: lo half accumulated even h, hi half odd h
    float* out = g_feats + (size_t)(tok0 + tid) * NL;
#pragma unroll
    for (int l = 0; l < NL; l++) {
        float lo, hi;
        asm("mov.b64 {%0, %1}, %2;" : "=f"(lo), "=f"(hi) : "l"(acc[l]));
        out[l] = lo + hi + __ldg(bias + l);
    }
}

// ---------------------------------------------------------------------------
// dtype-agnostic mask length (prefix mask; 1-byte bool or 4-byte int/float).
// ---------------------------------------------------------------------------
__device__ __forceinline__ int mask_len_warp(const unsigned char* mask, int b, int lane) {
    int c = 0;
    if (mask[1] != 0) {
        const uint4* mp = (const uint4*)(mask + (size_t)b * NS);
        uint4 mv = mp[lane];
        c = __dp4a((int)mv.x, 0x01010101, c);
        c = __dp4a((int)mv.y, 0x01010101, c);
        c = __dp4a((int)mv.z, 0x01010101, c);
        c = __dp4a((int)mv.w, 0x01010101, c);
    } else {
        const uint4* mp = (const uint4*)((const uint32_t*)mask + (size_t)b * NS);
#pragma unroll
        for (int k = 0; k < 4; k++) {
            uint4 mv = mp[lane * 4 + k];
            c += (mv.x != 0u) + (mv.y != 0u) + (mv.z != 0u) + (mv.w != 0u);
        }
    }
#pragma unroll
    for (int o = 16; o > 0; o >>= 1) c += __shfl_xor_sync(0xffffffffu, c, o);
    return c;
}

// ---------------------------------------------------------------------------
// Phase 2a: per-(batch,chunk) 9x9 log-semiring transfer matrix.
// Block = one (b, c); 3 warps; warp g: lanes 0..26 hold basis row r = 3g+lane/9,
// col j = lane%9, exp domain with renorm every 8 steps.
// ---------------------------------------------------------------------------
__global__ __launch_bounds__(96) void crf_chunk_kernel(
    const float* __restrict__ trans, const unsigned char* __restrict__ mask)
{
    __shared__ float s_ef[CHS + 1][NL];      // exp(feats) window (+1 for prefetch)

    int bx   = blockIdx.x;
    int b    = bx >> 3, c = bx & 7;
    int tid  = threadIdx.x;
    int lane = tid & 31;
    int wid  = tid >> 5;
    int t0   = c * CHS;

    const float* fb = g_feats + (size_t)b * NS * NL;

    for (int i = tid; i < (CHS + 1) * NL; i += 96) {
        int t = min(t0 + i / NL, NS - 1);
        s_ef[i / NL][i % NL] = __expf(fb[t * NL + i % NL]);
    }
    int len = mask_len_warp(mask, b, lane);
    __syncthreads();

    int jl = lane < 27 ? lane : 26;          // lanes 27..31 mirror lane 26
    int rl = jl / 9, j = jl % 9;
    int r  = wid * 3 + rl;
    int base = rl * 9;

    float Ecol[NL];
#pragma unroll
    for (int i = 0; i < NL; i++) Ecol[i] = __expf(__ldg(trans + i * NL + j));

    float q = (j == r) ? 1.0f : 0.0f;        // basis row r, exp domain
    float C = 0.0f;

    int tstart = (c == 0) ? 1 : t0;
    int tend   = min(t0 + CHS, len);

    float eft = s_ef[tstart - t0][j];
    for (int t = tstart; t < tend; t++) {
        float efn = s_ef[t + 1 - t0][j];
        float q0 = __shfl_sync(0xffffffffu, q, base + 0);
        float q1 = __shfl_sync(0xffffffffu, q, base + 1);
        float q2 = __shfl_sync(0xffffffffu, q, base + 2);
        float q3 = __shfl_sync(0xffffffffu, q, base + 3);
        float q4 = __shfl_sync(0xffffffffu, q, base + 4);
        float q5 = __shfl_sync(0xffffffffu, q, base + 5);
        float q6 = __shfl_sync(0xffffffffu, q, base + 6);
        float q7 = __shfl_sync(0xffffffffu, q, base + 7);
        float q8 = __shfl_sync(0xffffffffu, q, base + 8);
        float p  = ((q0*Ecol[0] + q1*Ecol[1]) + (q2*Ecol[2] + q3*Ecol[3]))
                 + ((q4*Ecol[4] + q5*Ecol[5]) + (q6*Ecol[6] + q7*Ecol[7]))
                 + q8*Ecol[8];
        float qn = p * eft;
        eft = efn;
        if ((t & 7) == 7) {                  // renorm (q0 > 0 after >=1 step)
            C += __logf(q0);
            qn *= __fdividef(1.0f, q0);
        }
        q = qn;
    }
    if (lane < 27)
        g_M[bx * 81 + r * NL + j] = C + __logf(q);
}

// ---------------------------------------------------------------------------
// Phase 2b: fold alpha0 through the 8 chunk matrices (warp 0) + gold-path
// score (warp 1); writes per-batch NLL.
// ---------------------------------------------------------------------------
__global__ __launch_bounds__(64) void crf_combine_kernel(
    const float* __restrict__ startv, const float* __restrict__ endv,
    const float* __restrict__ trans, const int* __restrict__ labels,
    const unsigned char* __restrict__ mask)
{
    __shared__ float s_M[NCH][81];
    __shared__ float s_score, s_logden;

    int b    = blockIdx.x;
    int tid  = threadIdx.x;
    int lane = tid & 31;
    int wid  = tid >> 5;

    const float* fb = g_feats + (size_t)b * NS * NL;

    for (int i = tid; i < NCH * 81; i += 64)
        s_M[i / 81][i % 81] = g_M[b * NCH * 81 + i];
    int len = mask_len_warp(mask, b, lane);
    __syncthreads();

    if (wid == 0) {
        int j = lane < 9 ? lane : 8;
        float v = __ldg(startv + j) + fb[j];     // log alpha_0
        for (int cc = 0; cc < NCH; cc++) {
            if (cc * CHS < len) {
                float x0 = __shfl_sync(0xffffffffu, v, 0) + s_M[cc][0*NL + j];
                float x1 = __shfl_sync(0xffffffffu, v, 1) + s_M[cc][1*NL + j];
                float x2 = __shfl_sync(0xffffffffu, v, 2) + s_M[cc][2*NL + j];
                float x3 = __shfl_sync(0xffffffffu, v, 3) + s_M[cc][3*NL + j];
                float x4 = __shfl_sync(0xffffffffu, v, 4) + s_M[cc][4*NL + j];
                float x5 = __shfl_sync(0xffffffffu, v, 5) + s_M[cc][5*NL + j];
                float x6 = __shfl_sync(0xffffffffu, v, 6) + s_M[cc][6*NL + j];
                float x7 = __shfl_sync(0xffffffffu, v, 7) + s_M[cc][7*NL + j];
                float x8 = __shfl_sync(0xffffffffu, v, 8) + s_M[cc][8*NL + j];
                float m = fmaxf(fmaxf(fmaxf(fmaxf(x0,x1),fmaxf(x2,x3)),
                                       fmaxf(fmaxf(x4,x5),fmaxf(x6,x7))), x8);
                float s = ((__expf(x0-m)+__expf(x1-m)) + (__expf(x2-m)+__expf(x3-m)))
                        + ((__expf(x4-m)+__expf(x5-m)) + (__expf(x6-m)+__expf(x7-m)))
                        + __expf(x8-m);
                v = m + __logf(s);
            }
        }
        float t = (lane < 9) ? v + __ldg(endv + j) : -3.0e38f;
        float m = t;
#pragma unroll
        for (int o = 16; o > 0; o >>= 1) m = fmaxf(m, __shfl_xor_sync(0xffffffffu, m, o));
        float e = (lane < 9) ? __expf(t - m) : 0.0f;
#pragma unroll
        for (int o = 16; o > 0; o >>= 1) e += __shfl_xor_sync(0xffffffffu, e, o);
        if (lane == 0) s_logden = m + __logf(e);
    } else {
        // gold-path score
        const int* lab = labels + (size_t)b * NS;
        float sc = 0.0f;
        for (int t = lane; t < NS; t += 32) {
            if (t >= 1 && t < len) {
                int lp = __ldg(lab + t - 1);
                int lc = __ldg(lab + t);
                sc += __ldg(trans + lp * NL + lc) + fb[t * NL + lc];
            }
        }
        if (lane == 0) {
            int l0 = __ldg(lab);
            sc += __ldg(startv + l0) + fb[l0];
            sc += __ldg(endv + __ldg(lab + len - 1));
        }
#pragma unroll
        for (int o = 16; o > 0; o >>= 1)
            sc += __shfl_xor_sync(0xffffffffu, sc, o);
        if (lane == 0) s_score = sc;
    }
    __syncthreads();
    if (tid == 0) g_nll[b] = s_logden - s_score;
}

// ---------------------------------------------------------------------------
// Phase 3: mean over batch -> scalar output
// ---------------------------------------------------------------------------
__global__ void reduce_kernel(float* out) {
    int tid = threadIdx.x;                   // 64 threads
    float v = g_nll[tid];
#pragma unroll
    for (int o = 16; o > 0; o >>= 1)
        v += __shfl_xor_sync(0xffffffffu, v, o);
    __shared__ float s[2];
    if ((tid & 31) == 0) s[tid >> 5] = v;
    __syncthreads();
    if (tid == 0) out[0] = (s[0] + s[1]) * (1.0f / NB);
}

extern "C" void kernel_launch(void* const* d_in, const int* in_sizes, int n_in,
                              void* d_out, int out_size) {
    const float*         hidden = (const float*)d_in[0];
    const float*         W      = (const float*)d_in[1];
    const float*         bias   = (const float*)d_in[2];
    const float*         startv = (const float*)d_in[3];
    const float*         endv   = (const float*)d_in[4];
    const float*         trans  = (const float*)d_in[5];
    const int*           labels = (const int*)d_in[6];
    const unsigned char* mask   = (const unsigned char*)d_in[7];

    gemm_kernel<<<NB * NS / GT, GT>>>(hidden, W, bias);
    crf_chunk_kernel<<<NB * NCH, 96>>>(trans, mask);
    crf_combine_kernel<<<NB, 64>>>(startv, endv, trans, labels, mask);
    reduce_kernel<<<1, 64>>>((float*)d_out);
}

// round 12
// speedup vs baseline: 1.2804x; 1.2804x over previous
#include <cuda_runtime.h>
#include <cstdint>

#define NB 64
#define NS 512
#define NH 768
#define NL 9
#define NCH 8
#define CHS 64

typedef unsigned long long ull;

// scratch (static device globals — no allocation)
__device__ float g_feats[NB * NS * NL];
__device__ float g_M[NB * NCH * 81];     // per-(batch,chunk) 9x9 log transfer matrices

__device__ __forceinline__ ull ffma2(ull a, ull b, ull c) {
    ull d;
    asm("fma.rn.f32x2 %0, %1, %2, %3;" : "=l"(d) : "l"(a), "l"(b), "l"(c));
    return d;
}

// ---------------------------------------------------------------------------
// Phase 1: feats[tok][l] = hidden[tok] . W[l] + b[l]
// Warp = 4 tokens (halves W-smem crossbar traffic vs 2), W staged in smem,
// packed f32x2 FMA over adjacent k-dims, next-chunk hidden prefetch in regs.
// L1 budget: W LDS ~12K cyc/SM + hidden LDG ~11K cyc/SM ~= DRAM floor.
// Also zeroes out[0] for the downstream atomic mean.
// ---------------------------------------------------------------------------
__global__ __launch_bounds__(256, 2) void gemm_kernel(
    const float* __restrict__ hidden, const float* __restrict__ W,
    const float* __restrict__ bias, float* __restrict__ out)
{
    __shared__ float s_w[NL * NH];               // 27648 B

    int tid  = threadIdx.x;
    int lane = tid & 31;
    int wid  = tid >> 5;
    int tok0 = (blockIdx.x * 8 + wid) * 4;

    if (blockIdx.x == 0 && tid == 0) out[0] = 0.0f;

    // issue chunk-0 hidden prefetch before W staging (independent LDGs)
    const float* hb = hidden + (size_t)tok0 * NH;
    ulonglong2 hv[4], hvn[4];
#pragma unroll
    for (int t = 0; t < 4; t++)
        hv[t] = __ldg((const ulonglong2*)(hb + t * NH) + lane);

    // cooperative W stage (1728 float4 over 256 threads)
    for (int i = tid; i < NL * NH / 4; i += 256)
        ((float4*)s_w)[i] = __ldg((const float4*)W + i);
    __syncthreads();

    ull acc[4][NL];
#pragma unroll
    for (int t = 0; t < 4; t++)
#pragma unroll
        for (int l = 0; l < NL; l++) acc[t][l] = 0ull;

#pragma unroll
    for (int c = 0; c < 6; c++) {
        if (c < 5) {                             // prefetch next hidden chunk
#pragma unroll
            for (int t = 0; t < 4; t++)
                hvn[t] = __ldg((const ulonglong2*)(hb + t * NH + (c + 1) * 128) + lane);
        }
#pragma unroll
        for (int l = 0; l < NL; l++) {
            ulonglong2 wv = *(const ulonglong2*)(s_w + l * NH + c * 128 + lane * 4);
#pragma unroll
            for (int t = 0; t < 4; t++) {
                acc[t][l] = ffma2(hv[t].x, wv.x, acc[t][l]);
                acc[t][l] = ffma2(hv[t].y, wv.y, acc[t][l]);
            }
        }
#pragma unroll
        for (int t = 0; t < 4; t++) hv[t] = hvn[t];
    }

#pragma unroll
    for (int t = 0; t < 4; t++) {
#pragma unroll
        for (int l = 0; l < NL; l++) {
            float lo, hi;
            asm("mov.b64 {%0, %1}, %2;" : "=f"(lo), "=f"(hi) : "l"(acc[t][l]));
            float v = lo + hi;
#pragma unroll
            for (int o = 16; o > 0; o >>= 1)
                v += __shfl_xor_sync(0xffffffffu, v, o);
            int oidx = t * NL + l;               // 0..35
            if (lane == (oidx & 31))
                g_feats[(size_t)(tok0 + t) * NL + l] = v + __ldg(bias + l);
        }
    }
}

// ---------------------------------------------------------------------------
// dtype-agnostic mask length (prefix mask; 1-byte bool or 4-byte int/float).
// ---------------------------------------------------------------------------
__device__ __forceinline__ int mask_len_warp(const unsigned char* mask, int b, int lane) {
    int c = 0;
    if (mask[1] != 0) {
        const uint4* mp = (const uint4*)(mask + (size_t)b * NS);
        uint4 mv = mp[lane];
        c = __dp4a((int)mv.x, 0x01010101, c);
        c = __dp4a((int)mv.y, 0x01010101, c);
        c = __dp4a((int)mv.z, 0x01010101, c);
        c = __dp4a((int)mv.w, 0x01010101, c);
    } else {
        const uint4* mp = (const uint4*)((const uint32_t*)mask + (size_t)b * NS);
#pragma unroll
        for (int k = 0; k < 4; k++) {
            uint4 mv = mp[lane * 4 + k];
            c += (mv.x != 0u) + (mv.y != 0u) + (mv.z != 0u) + (mv.w != 0u);
        }
    }
#pragma unroll
    for (int o = 16; o > 0; o >>= 1) c += __shfl_xor_sync(0xffffffffu, c, o);
    return c;
}

// ---------------------------------------------------------------------------
// Phase 2a: per-(batch,chunk) 9x9 log-semiring transfer matrix.
// Block = one (b, c); 3 warps; warp g: lanes 0..26 hold basis row r = 3g+lane/9,
// col j = lane%9, exp domain with renorm every 8 steps.
// ---------------------------------------------------------------------------
__global__ __launch_bounds__(96) void crf_chunk_kernel(
    const float* __restrict__ trans, const unsigned char* __restrict__ mask)
{
    __shared__ float s_ef[CHS + 1][NL];          // exp(feats) window

    int bx   = blockIdx.x;
    int b    = bx >> 3, c = bx & 7;
    int tid  = threadIdx.x;
    int lane = tid & 31;
    int wid  = tid >> 5;
    int t0   = c * CHS;

    const float* fb = g_feats + (size_t)b * NS * NL;

    for (int i = tid; i < (CHS + 1) * NL; i += 96) {
        int t = min(t0 + i / NL, NS - 1);
        s_ef[i / NL][i % NL] = __expf(fb[t * NL + i % NL]);
    }
    int len = mask_len_warp(mask, b, lane);
    __syncthreads();

    int jl = lane < 27 ? lane : 26;              // lanes 27..31 mirror lane 26
    int rl = jl / 9, j = jl % 9;
    int r  = wid * 3 + rl;
    int base = rl * 9;

    float Ecol[NL];
#pragma unroll
    for (int i = 0; i < NL; i++) Ecol[i] = __expf(__ldg(trans + i * NL + j));

    float q = (j == r) ? 1.0f : 0.0f;            // basis row r, exp domain
    float C = 0.0f;

    int tstart = (c == 0) ? 1 : t0;
    int tend   = min(t0 + CHS, len);

    float eft = s_ef[tstart - t0][j];
    for (int t = tstart; t < tend; t++) {
        float efn = s_ef[t + 1 - t0][j];
        float q0 = __shfl_sync(0xffffffffu, q, base + 0);
        float q1 = __shfl_sync(0xffffffffu, q, base + 1);
        float q2 = __shfl_sync(0xffffffffu, q, base + 2);
        float q3 = __shfl_sync(0xffffffffu, q, base + 3);
        float q4 = __shfl_sync(0xffffffffu, q, base + 4);
        float q5 = __shfl_sync(0xffffffffu, q, base + 5);
        float q6 = __shfl_sync(0xffffffffu, q, base + 6);
        float q7 = __shfl_sync(0xffffffffu, q, base + 7);
        float q8 = __shfl_sync(0xffffffffu, q, base + 8);
        float p  = ((q0*Ecol[0] + q1*Ecol[1]) + (q2*Ecol[2] + q3*Ecol[3]))
                 + ((q4*Ecol[4] + q5*Ecol[5]) + (q6*Ecol[6] + q7*Ecol[7]))
                 + q8*Ecol[8];
        float qn = p * eft;
        eft = efn;
        if ((t & 7) == 7) {                      // renorm (q0 > 0 after >=1 step)
            C += __logf(q0);
            qn *= __fdividef(1.0f, q0);
        }
        q = qn;
    }
    if (lane < 27)
        g_M[bx * 81 + r * NL + j] = C + __logf(q);
}

// ---------------------------------------------------------------------------
// Phase 2b: fold alpha0 through the 8 chunk matrices (warp 0) + gold-path
// score (warp 1); atomically accumulates mean NLL into out[0].
// ---------------------------------------------------------------------------
__global__ __launch_bounds__(64) void crf_combine_kernel(
    const float* __restrict__ startv, const float* __restrict__ endv,
    const float* __restrict__ trans, const int* __restrict__ labels,
    const unsigned char* __restrict__ mask, float* __restrict__ out)
{
    __shared__ float s_M[NCH][81];
    __shared__ float s_score, s_logden;

    int b    = blockIdx.x;
    int tid  = threadIdx.x;
    int lane = tid & 31;
    int wid  = tid >> 5;

    const float* fb = g_feats + (size_t)b * NS * NL;

    for (int i = tid; i < NCH * 81; i += 64)
        s_M[i / 81][i % 81] = g_M[b * NCH * 81 + i];
    int len = mask_len_warp(mask, b, lane);
    __syncthreads();

    if (wid == 0) {
        int j = lane < 9 ? lane : 8;
        float v = __ldg(startv + j) + fb[j];     // log alpha_0
        for (int cc = 0; cc < NCH; cc++) {
            if (cc * CHS < len) {
                float x0 = __shfl_sync(0xffffffffu, v, 0) + s_M[cc][0*NL + j];
                float x1 = __shfl_sync(0xffffffffu, v, 1) + s_M[cc][1*NL + j];
                float x2 = __shfl_sync(0xffffffffu, v, 2) + s_M[cc][2*NL + j];
                float x3 = __shfl_sync(0xffffffffu, v, 3) + s_M[cc][3*NL + j];
                float x4 = __shfl_sync(0xffffffffu, v, 4) + s_M[cc][4*NL + j];
                float x5 = __shfl_sync(0xffffffffu, v, 5) + s_M[cc][5*NL + j];
                float x6 = __shfl_sync(0xffffffffu, v, 6) + s_M[cc][6*NL + j];
                float x7 = __shfl_sync(0xffffffffu, v, 7) + s_M[cc][7*NL + j];
                float x8 = __shfl_sync(0xffffffffu, v, 8) + s_M[cc][8*NL + j];
                float m = fmaxf(fmaxf(fmaxf(fmaxf(x0,x1),fmaxf(x2,x3)),
                                       fmaxf(fmaxf(x4,x5),fmaxf(x6,x7))), x8);
                float s = ((__expf(x0-m)+__expf(x1-m)) + (__expf(x2-m)+__expf(x3-m)))
                        + ((__expf(x4-m)+__expf(x5-m)) + (__expf(x6-m)+__expf(x7-m)))
                        + __expf(x8-m);
                v = m + __logf(s);
            }
        }
        float t = (lane < 9) ? v + __ldg(endv + j) : -3.0e38f;
        float m = t;
#pragma unroll
        for (int o = 16; o > 0; o >>= 1) m = fmaxf(m, __shfl_xor_sync(0xffffffffu, m, o));
        float e = (lane < 9) ? __expf(t - m) : 0.0f;
#pragma unroll
        for (int o = 16; o > 0; o >>= 1) e += __shfl_xor_sync(0xffffffffu, e, o);
        if (lane == 0) s_logden = m + __logf(e);
    } else {
        // gold-path score
        const int* lab = labels + (size_t)b * NS;
        float sc = 0.0f;
        for (int t = lane; t < NS; t += 32) {
            if (t >= 1 && t < len) {
                int lp = __ldg(lab + t - 1);
                int lc = __ldg(lab + t);
                sc += __ldg(trans + lp * NL + lc) + fb[t * NL + lc];
            }
        }
        if (lane == 0) {
            int l0 = __ldg(lab);
            sc += __ldg(startv + l0) + fb[l0];
            sc += __ldg(endv + __ldg(lab + len - 1));
        }
#pragma unroll
        for (int o = 16; o > 0; o >>= 1)
            sc += __shfl_xor_sync(0xffffffffu, sc, o);
        if (lane == 0) s_score = sc;
    }
    __syncthreads();
    if (tid == 0)
        atomicAdd(out, (s_logden - s_score) * (1.0f / NB));
}

extern "C" void kernel_launch(void* const* d_in, const int* in_sizes, int n_in,
                              void* d_out, int out_size) {
    const float*         hidden = (const float*)d_in[0];
    const float*         W      = (const float*)d_in[1];
    const float*         bias   = (const float*)d_in[2];
    const float*         startv = (const float*)d_in[3];
    const float*         endv   = (const float*)d_in[4];
    const float*         trans  = (const float*)d_in[5];
    const int*           labels = (const int*)d_in[6];
    const unsigned char* mask   = (const unsigned char*)d_in[7];
    float*               out    = (float*)d_out;

    gemm_kernel<<<NB * NS / 32, 256>>>(hidden, W, bias, out);
    crf_chunk_kernel<<<NB * NCH, 96>>>(trans, mask);
    crf_combine_kernel<<<NB, 64>>>(startv, endv, trans, labels, mask, out);
}